// round 15
// baseline (speedup 1.0000x reference)
#include <cuda_runtime.h>

#define BB 8
#define CC 64
#define WH 214272             // 496*432
#define WH4 53568             // WH/4
#define WH32 6696             // WH/32
#define CHUNKS 1674           // WH/128 chunks per batch (norm granularity)
#define BPB 837               // stats blocks per batch (256 positions each)
#define NBLOCKS (BB * BPB)
#define EPSF 0.001f
#define NPAD 68               // norm sVal row pitch (16B-aligned float4 rows)
#define NBKT 16               // atomic buckets for channel sums

// Scratch (device globals — no allocations allowed).
__device__ float        g_S1p[NBKT][CC];
__device__ float        g_S2p[NBKT][CC];
__device__ int          g_n[BB];
__device__ float        g_inv[CC];
__device__ unsigned int g_maskbits[BB * WH32];   // 1 bit / position (214 KB)
__device__ unsigned int g_cbase[BB * CHUNKS];    // compact base (positions) per 128-chunk
__device__ float4       g_compact[6856704];      // 25% density capacity (~110 MB)
__device__ unsigned int g_alloc;
__device__ unsigned int g_done;

// ---------------------------------------------------------------------------
// Pass 1: per-channel sums + nonzero count + mask bitmap + compaction.
// 512 threads, 256 positions/block (1KB-per-plane reads: R3's DRAM-friendly
// granularity), each thread owns 32 channels of ONE position (v[32], ~55
// regs, no spills, 2 blocks/SM = 32 warps). Each block covers TWO 128-pos
// chunks (norm's granularity): one atomic allocates both, per-chunk bases
// recorded. Reduction reuses a 128-row transpose buffer in two phases.
// Last block runs finalize inline.
// ---------------------------------------------------------------------------
__global__ void __launch_bounds__(512, 2) stats_kernel(const float* __restrict__ x) {
    const int t   = threadIdx.x;
    const int b   = blockIdx.x / BPB;
    const int bib = blockIdx.x % BPB;            // 256-pos block within batch
    const int p   = t & 255;                     // position within block
    const int cg  = t >> 8;                      // channel group (0: 0-31, 1: 32-63)
    const float* xb = x + (size_t)b * CC * WH + (size_t)bib * 256 + p
                        + (size_t)(cg * 32) * WH;

    float v[32];
    float csum = 0.0f;
#pragma unroll
    for (int k = 0; k < 32; k++) {
        v[k] = __ldcs(&xb[(size_t)k * WH]);
        csum += v[k];
    }

    __shared__ float         sm[128 * 65];       // 33.3 KB transpose (2 phases)
    __shared__ float         sCs[2][256];
    __shared__ float         r1[512];
    __shared__ float         r2[512];
    __shared__ unsigned      sWd[8];
    __shared__ int           sPc[8];
    __shared__ int           sPref[8];
    __shared__ unsigned      sBaseS[2];
    __shared__ unsigned char sRank8[256];

    sCs[cg][p] = csum;
    __syncthreads();

    // mask per position (warps 0-7 hold positions 0..255 in order)
    if (t < 256) {
        bool m = (sCs[0][t] + sCs[1][t]) != 0.0f;
        unsigned ballot = __ballot_sync(0xffffffffu, m);
        if ((t & 31) == 0) {
            int w = t >> 5;
            sWd[w] = ballot;
            sPc[w] = __popc(ballot);
            g_maskbits[b * WH32 + bib * 8 + w] = ballot;
        }
    }
    __syncthreads();

    if (t == 0) {
        int pr = 0;
#pragma unroll
        for (int w = 0; w < 4; w++) { sPref[w] = pr; pr += sPc[w]; }
        int cnt0 = pr;
        pr = 0;
#pragma unroll
        for (int w = 4; w < 8; w++) { sPref[w] = pr; pr += sPc[w]; }
        int cnt1 = pr;
        unsigned base = atomicAdd(&g_alloc, (unsigned)(cnt0 + cnt1));
        sBaseS[0] = base;
        sBaseS[1] = base + (unsigned)cnt0;
        g_cbase[b * CHUNKS + bib * 2]     = base;
        g_cbase[b * CHUNKS + bib * 2 + 1] = base + (unsigned)cnt0;
        atomicAdd(&g_n[b], cnt0 + cnt1);
    }
    __syncthreads();
    if (t < 256) {
        unsigned w = sWd[t >> 5];
        int bit = t & 31;
        sRank8[t] = (unsigned char)(sPref[t >> 5] + __popc(w & ((1u << bit) - 1u)));
    }
    __syncthreads();

    // compact store from registers: each masked position written by 2 threads
    {
        unsigned w = sWd[p >> 5];
        if ((w >> (p & 31)) & 1u) {
            int k = p >> 7;                      // which 128-chunk
            float4* dst = g_compact + ((size_t)sBaseS[k] + sRank8[p]) * 16 + cg * 8;
#pragma unroll
            for (int q = 0; q < 8; q++)
                __stcs(dst + q, make_float4(v[4*q], v[4*q+1], v[4*q+2], v[4*q+3]));
        }
    }

    // per-channel reduction: two 128-position phases through the 33KB buffer
    const int c  = t & 63;
    const int g8 = t >> 6;                       // 0..7: 8 groups x 16 rows
    float a1 = 0.0f, a2 = 0.0f;
#pragma unroll
    for (int phase = 0; phase < 2; phase++) {
        if ((p >> 7) == phase) {
            const int row = p & 127;
#pragma unroll
            for (int k = 0; k < 32; k++) sm[row * 65 + cg * 32 + k] = v[k];
        }
        __syncthreads();
#pragma unroll
        for (int i = 0; i < 16; i++) {
            float val = sm[(g8 * 16 + i) * 65 + c];
            a1 += val;
            a2 += val * val;
        }
        __syncthreads();
    }

    r1[t] = a1;
    r2[t] = a2;
    __syncthreads();

    if (t < CC) {
        float s1 = 0.0f, s2 = 0.0f;
#pragma unroll
        for (int q = 0; q < 8; q++) { s1 += r1[t + 64 * q]; s2 += r2[t + 64 * q]; }
        const int bkt = blockIdx.x & (NBKT - 1);
        atomicAdd(&g_S1p[bkt][t], s1);
        atomicAdd(&g_S2p[bkt][t], s2);
    }

    // ---- merged finalize: last block computes inv + resets state -----------
    __shared__ bool isLast;
    __shared__ int  spad[BB];
    __shared__ int  sN;
    __threadfence();
    if (t == 0) {
        unsigned int d = atomicAdd(&g_done, 1u);
        isLast = (d == (unsigned int)(NBLOCKS - 1));
    }
    __syncthreads();
    if (!isLast) return;

    if (t == 0) {
        g_done = 0;
        g_alloc = 0;
        int mx = 0;
#pragma unroll
        for (int bb = 0; bb < BB; bb++) mx = max(mx, g_n[bb]);
        sN = mx;
#pragma unroll
        for (int bb = 0; bb < BB; bb++) {
            spad[bb] = mx - g_n[bb];
            g_n[bb] = 0;
        }
    }
    __syncthreads();
    if (t < CC) {
        float s1 = 0.0f, s2 = 0.0f;
#pragma unroll
        for (int q = 0; q < NBKT; q++) {
            s1 += g_S1p[q][t];
            s2 += g_S2p[q][t];
            g_S1p[q][t] = 0.0f;
            g_S2p[q][t] = 0.0f;
        }
#pragma unroll
        for (int bb = 0; bb < BB; bb++) {
            float x00 = x[(size_t)bb * CC * WH + (size_t)t * WH];
            float pd = (float)spad[bb];
            s1 += pd * x00;
            s2 += pd * x00 * x00;
        }
        float count = (float)BB * (float)sN;
        float mean = s1 / count;
        float var  = s2 / count - mean * mean;
        g_inv[t] = rsqrtf(var + EPSF);
    }
}

// ---------------------------------------------------------------------------
// Pass 2: normalize WITHOUT reading x (unchanged: ~78us, near its
// write-bound floor). One block per 128-position chunk; coalesced float4
// load of compact values into smem; hoisted mask/rank logic; dense emit.
// ---------------------------------------------------------------------------
__global__ void __launch_bounds__(256) norm_kernel(float* __restrict__ out) {
    const int b     = blockIdx.y;
    const int chunk = blockIdx.x;       // 0..1673
    const int t     = threadIdx.x;

    __shared__ __align__(16) float         sVal[128 * NPAD];
    __shared__ __align__(16) unsigned char sRank8[128];
    __shared__ unsigned      sW4[4];
    __shared__ int           sPc[4];
    __shared__ int           sPref[4];
    __shared__ int           sCnt_;
    __shared__ unsigned      sBase_;
    __shared__ float         sInv[CC];

    if (t < 4) {
        unsigned w = g_maskbits[b * WH32 + chunk * 4 + t];
        sW4[t] = w;
        sPc[t] = __popc(w);
    }
    if (t >= 64 && t < 128) sInv[t - 64] = g_inv[t - 64];
    __syncthreads();
    if (t == 0) {
        sPref[0] = 0;
        sPref[1] = sPc[0];
        sPref[2] = sPc[0] + sPc[1];
        sPref[3] = sPc[0] + sPc[1] + sPc[2];
        sCnt_  = sPref[3] + sPc[3];
        sBase_ = g_cbase[b * CHUNKS + chunk];
    }
    __syncthreads();
    if (t < 128) {
        unsigned w = sW4[t >> 5];
        int bit = t & 31;
        sRank8[t] = (unsigned char)(sPref[t >> 5] + __popc(w & ((1u << bit) - 1u)));
    }
    {
        const int E4 = sCnt_ * 16;      // float4 count
        const float4* gin = g_compact + (size_t)sBase_ * 16;
        for (int i = t; i < E4; i += 256) {
            float4 vv = __ldcs(gin + i);
            *reinterpret_cast<float4*>(&sVal[(i >> 4) * NPAD + (i & 15) * 4]) = vv;
        }
    }
    __syncthreads();

    // hoisted per-thread invariants (independent of channel loop)
    const int p4 = t & 31;
    const int p  = p4 * 4;
    const unsigned w = sW4[p >> 5];
    const int sh = p & 31;
    const bool b0 = (w >> sh)       & 1u;
    const bool b1 = (w >> (sh + 1)) & 1u;
    const bool b2 = (w >> (sh + 2)) & 1u;
    const bool b3 = (w >> (sh + 3)) & 1u;
    const uchar4 rk = *reinterpret_cast<const uchar4*>(&sRank8[p]);
    float4* o4 = reinterpret_cast<float4*>(out)
               + (((size_t)b * CC * WH + (size_t)chunk * 128) >> 2) + p4;

#pragma unroll
    for (int j = 0; j < 8; j++) {
        const int c = j * 8 + (t >> 5);
        const float inv = sInv[c];
        float4 o = make_float4(0.0f, 0.0f, 0.0f, 0.0f);
        if (b0) o.x = sVal[rk.x * NPAD + c] * inv;
        if (b1) o.y = sVal[rk.y * NPAD + c] * inv;
        if (b2) o.z = sVal[rk.z * NPAD + c] * inv;
        if (b3) o.w = sVal[rk.w * NPAD + c] * inv;
        __stcs(o4 + (size_t)c * WH4, o);
    }
}

// ---------------------------------------------------------------------------
extern "C" void kernel_launch(void* const* d_in, const int* in_sizes, int n_in,
                              void* d_out, int out_size) {
    const float* x = (const float*)d_in[0];
    float* out = (float*)d_out;

    stats_kernel<<<NBLOCKS, 512>>>(x);
    dim3 ngrid(CHUNKS, BB);               // (1674, 8)
    norm_kernel<<<ngrid, 256>>>(out);
}

// round 16
// speedup vs baseline: 1.1320x; 1.1320x over previous
#include <cuda_runtime.h>

#define BB 8
#define CC 64
#define WH 214272             // 496*432
#define WH4 53568             // WH/4
#define WH32 6696             // WH/32
#define CHUNKS 1674           // WH/128 chunks per batch
#define NBLOCKS (BB * CHUNKS) // stats: one block per 128-position chunk
#define EPSF 0.001f
#define NPAD 68               // norm sVal row pitch (16B-aligned float4 rows)
#define NBKT 16               // atomic buckets for channel sums

// Scratch (device globals — no allocations allowed).
__device__ float        g_S1p[NBKT][CC];
__device__ float        g_S2p[NBKT][CC];
__device__ int          g_n[BB];
__device__ float        g_inv[CC];
__device__ unsigned int g_maskbits[BB * WH32];   // 1 bit / position (214 KB)
__device__ unsigned int g_cbase[BB * CHUNKS];    // compact base (positions) per chunk
__device__ float4       g_compact[6856704];      // 25% density capacity (~110 MB)
__device__ unsigned int g_alloc;
__device__ unsigned int g_done;

// ---------------------------------------------------------------------------
// Pass 1 (R12/13 config — best measured with compaction): block = 128
// positions x 64 channels, each thread owns 32 channels of ONE position
// (v[32], 4 blocks/SM). Compact values written with __stcg (L2-retained,
// ~44MB fits L2) so the write stream is absorbed by L2 instead of forcing
// eager DRAM writebacks interleaved with the read stream (__stcs in R10-R15
// cost every compaction variant ~30% read efficiency). Last block finalizes.
// ---------------------------------------------------------------------------
__global__ void __launch_bounds__(256, 4) stats_kernel(const float* __restrict__ x) {
    const int t   = threadIdx.x;
    const int b   = blockIdx.x / CHUNKS;
    const int cib = blockIdx.x % CHUNKS;         // chunk within batch
    const int p   = t & 127;                     // position within chunk
    const int cg  = t >> 7;                      // channel group (0: ch0-31, 1: ch32-63)
    const float* xb = x + (size_t)b * CC * WH + (size_t)cib * 128 + p
                        + (size_t)(cg * 32) * WH;

    float v[32];
    float csum = 0.0f;
#pragma unroll
    for (int k = 0; k < 32; k++) {
        v[k] = __ldcs(&xb[(size_t)k * WH]);
        csum += v[k];
    }

    __shared__ float         sm[128 * 65];       // 33.3 KB transpose (padded)
    __shared__ float         sCs[2][128];
    __shared__ float         r1[256];
    __shared__ float         r2[256];
    __shared__ unsigned      sWd[4];
    __shared__ int           sPc[4];
    __shared__ int           sPref[4];
    __shared__ unsigned      sBase;
    __shared__ unsigned char sRank8[128];

    // transpose store (256 threads cover the full 128x64 tile)
#pragma unroll
    for (int k = 0; k < 32; k++) sm[p * 65 + cg * 32 + k] = v[k];
    sCs[cg][p] = csum;
    __syncthreads();

    // mask per position (warps 0-3 hold positions 0..127 in order)
    if (t < 128) {
        bool m = (sCs[0][t] + sCs[1][t]) != 0.0f;
        unsigned ballot = __ballot_sync(0xffffffffu, m);
        if ((t & 31) == 0) {
            int w = t >> 5;
            sWd[w] = ballot;
            sPc[w] = __popc(ballot);
            g_maskbits[b * WH32 + cib * 4 + w] = ballot;
        }
    }
    __syncthreads();

    if (t == 0) {
        sPref[0] = 0;
        sPref[1] = sPc[0];
        sPref[2] = sPc[0] + sPc[1];
        sPref[3] = sPc[0] + sPc[1] + sPc[2];
        int tot  = sPref[3] + sPc[3];
        sBase = atomicAdd(&g_alloc, (unsigned)tot);
        g_cbase[b * CHUNKS + cib] = sBase;
        atomicAdd(&g_n[b], tot);
    }
    __syncthreads();
    if (t < 128) {
        unsigned w = sWd[t >> 5];
        int bit = t & 31;
        sRank8[t] = (unsigned char)(sPref[t >> 5] + __popc(w & ((1u << bit) - 1u)));
    }
    __syncthreads();

    // compact store from registers (L2-retained): 2 threads per masked position
    {
        unsigned w = sWd[p >> 5];
        if ((w >> (p & 31)) & 1u) {
            float4* dst = g_compact + ((size_t)sBase + sRank8[p]) * 16 + cg * 8;
#pragma unroll
            for (int q = 0; q < 8; q++)
                __stcg(dst + q, make_float4(v[4*q], v[4*q+1], v[4*q+2], v[4*q+3]));
        }
    }

    // per-channel reduction (v dead from here; low pressure)
    const int c = t & 63;
    const int g = t >> 6;
    float a1 = 0.0f, a2 = 0.0f;
#pragma unroll
    for (int i = 0; i < 32; i++) {
        float val = sm[(g * 32 + i) * 65 + c];
        a1 += val;
        a2 += val * val;
    }
    r1[t] = a1;
    r2[t] = a2;
    __syncthreads();

    if (t < CC) {
        float s1 = r1[t] + r1[t + 64] + r1[t + 128] + r1[t + 192];
        float s2 = r2[t] + r2[t + 64] + r2[t + 128] + r2[t + 192];
        const int bkt = blockIdx.x & (NBKT - 1);
        atomicAdd(&g_S1p[bkt][t], s1);
        atomicAdd(&g_S2p[bkt][t], s2);
    }

    // ---- merged finalize: last block computes inv + resets state -----------
    __shared__ bool isLast;
    __shared__ int  spad[BB];
    __shared__ int  sN;
    __threadfence();
    if (t == 0) {
        unsigned int d = atomicAdd(&g_done, 1u);
        isLast = (d == (unsigned int)(NBLOCKS - 1));
    }
    __syncthreads();
    if (!isLast) return;

    if (t == 0) {
        g_done = 0;
        g_alloc = 0;
        int mx = 0;
#pragma unroll
        for (int bb = 0; bb < BB; bb++) mx = max(mx, g_n[bb]);
        sN = mx;
#pragma unroll
        for (int bb = 0; bb < BB; bb++) {
            spad[bb] = mx - g_n[bb];
            g_n[bb] = 0;
        }
    }
    __syncthreads();
    if (t < CC) {
        float s1 = 0.0f, s2 = 0.0f;
#pragma unroll
        for (int q = 0; q < NBKT; q++) {
            s1 += g_S1p[q][t];
            s2 += g_S2p[q][t];
            g_S1p[q][t] = 0.0f;
            g_S2p[q][t] = 0.0f;
        }
#pragma unroll
        for (int bb = 0; bb < BB; bb++) {
            float x00 = x[(size_t)bb * CC * WH + (size_t)t * WH];
            float pd = (float)spad[bb];
            s1 += pd * x00;
            s2 += pd * x00 * x00;
        }
        float count = (float)BB * (float)sN;
        float mean = s1 / count;
        float var  = s2 / count - mean * mean;
        g_inv[t] = rsqrtf(var + EPSF);
    }
}

// ---------------------------------------------------------------------------
// Pass 2: normalize WITHOUT reading x. One block per 128-position chunk;
// compact values loaded with __ldcg (should hit L2 since stats just wrote
// them with __stcg and out-stores are evict-first); hoisted mask/rank logic;
// dense emit with coalesced float4 stores.
// ---------------------------------------------------------------------------
__global__ void __launch_bounds__(256) norm_kernel(float* __restrict__ out) {
    const int b     = blockIdx.y;
    const int chunk = blockIdx.x;       // 0..1673
    const int t     = threadIdx.x;

    __shared__ __align__(16) float         sVal[128 * NPAD];
    __shared__ __align__(16) unsigned char sRank8[128];
    __shared__ unsigned      sW4[4];
    __shared__ int           sPc[4];
    __shared__ int           sPref[4];
    __shared__ int           sCnt_;
    __shared__ unsigned      sBase_;
    __shared__ float         sInv[CC];

    if (t < 4) {
        unsigned w = g_maskbits[b * WH32 + chunk * 4 + t];
        sW4[t] = w;
        sPc[t] = __popc(w);
    }
    if (t >= 64 && t < 128) sInv[t - 64] = g_inv[t - 64];
    __syncthreads();
    if (t == 0) {
        sPref[0] = 0;
        sPref[1] = sPc[0];
        sPref[2] = sPc[0] + sPc[1];
        sPref[3] = sPc[0] + sPc[1] + sPc[2];
        sCnt_  = sPref[3] + sPc[3];
        sBase_ = g_cbase[b * CHUNKS + chunk];
    }
    __syncthreads();
    if (t < 128) {
        unsigned w = sW4[t >> 5];
        int bit = t & 31;
        sRank8[t] = (unsigned char)(sPref[t >> 5] + __popc(w & ((1u << bit) - 1u)));
    }
    {
        const int E4 = sCnt_ * 16;      // float4 count
        const float4* gin = g_compact + (size_t)sBase_ * 16;
        for (int i = t; i < E4; i += 256) {
            float4 vv = __ldcg(gin + i);
            *reinterpret_cast<float4*>(&sVal[(i >> 4) * NPAD + (i & 15) * 4]) = vv;
        }
    }
    __syncthreads();

    // hoisted per-thread invariants (independent of channel loop)
    const int p4 = t & 31;
    const int p  = p4 * 4;
    const unsigned w = sW4[p >> 5];
    const int sh = p & 31;
    const bool b0 = (w >> sh)       & 1u;
    const bool b1 = (w >> (sh + 1)) & 1u;
    const bool b2 = (w >> (sh + 2)) & 1u;
    const bool b3 = (w >> (sh + 3)) & 1u;
    const uchar4 rk = *reinterpret_cast<const uchar4*>(&sRank8[p]);
    float4* o4 = reinterpret_cast<float4*>(out)
               + (((size_t)b * CC * WH + (size_t)chunk * 128) >> 2) + p4;

#pragma unroll
    for (int j = 0; j < 8; j++) {
        const int c = j * 8 + (t >> 5);
        const float inv = sInv[c];
        float4 o = make_float4(0.0f, 0.0f, 0.0f, 0.0f);
        if (b0) o.x = sVal[rk.x * NPAD + c] * inv;
        if (b1) o.y = sVal[rk.y * NPAD + c] * inv;
        if (b2) o.z = sVal[rk.z * NPAD + c] * inv;
        if (b3) o.w = sVal[rk.w * NPAD + c] * inv;
        __stcs(o4 + (size_t)c * WH4, o);
    }
}

// ---------------------------------------------------------------------------
extern "C" void kernel_launch(void* const* d_in, const int* in_sizes, int n_in,
                              void* d_out, int out_size) {
    const float* x = (const float*)d_in[0];
    float* out = (float*)d_out;

    stats_kernel<<<NBLOCKS, 256>>>(x);
    dim3 ngrid(CHUNKS, BB);               // (1674, 8)
    norm_kernel<<<ngrid, 256>>>(out);
}

// round 17
// speedup vs baseline: 1.1805x; 1.0428x over previous
#include <cuda_runtime.h>

#define BB 8
#define CC 64
#define WH 214272             // 496*432
#define WH4 53568             // WH/4
#define WH32 6696             // WH/32
#define CHUNKS 1674           // WH/128 chunks per batch
#define NBLOCKS (BB * CHUNKS) // stats: one block per 128-position chunk
#define EPSF 0.001f
#define NPAD 68               // norm sVal row pitch (16B-aligned float4 rows)
#define NBKT 16               // atomic buckets for channel sums

// Scratch (device globals — no allocations allowed).
// g_compact: STATIC per-chunk regions (capacity 128 positions each, 439 MB
// reserved, only ~44 MB touched/replay). No allocator atomic, no base table;
// base = chunkId * 128. Deterministic layout.
__device__ float        g_S1p[NBKT][CC];
__device__ float        g_S2p[NBKT][CC];
__device__ int          g_n[BB];
__device__ float        g_inv[CC];
__device__ unsigned int g_maskbits[BB * WH32];   // 1 bit / position (214 KB)
__device__ float4       g_compact[(size_t)NBLOCKS * 128 * 16];
__device__ unsigned int g_done;

// ---------------------------------------------------------------------------
// Pass 1: block = 128 positions x 64 channels, each thread owns 32 channels
// of ONE position (v[32], 4 blocks/SM). Compact values written with __stcg
// (L2-retained, read back by norm from L2). Static chunk bases remove the
// g_alloc ATOMG (~320cy) and cbase store from the per-block critical path.
// Last block runs finalize inline.
// ---------------------------------------------------------------------------
__global__ void __launch_bounds__(256, 4) stats_kernel(const float* __restrict__ x) {
    const int t   = threadIdx.x;
    const int b   = blockIdx.x / CHUNKS;
    const int cib = blockIdx.x % CHUNKS;         // chunk within batch
    const int p   = t & 127;                     // position within chunk
    const int cg  = t >> 7;                      // channel group (0: ch0-31, 1: ch32-63)
    const float* xb = x + (size_t)b * CC * WH + (size_t)cib * 128 + p
                        + (size_t)(cg * 32) * WH;

    float v[32];
    float csum = 0.0f;
#pragma unroll
    for (int k = 0; k < 32; k++) {
        v[k] = __ldcs(&xb[(size_t)k * WH]);
        csum += v[k];
    }

    __shared__ float         sm[128 * 65];       // 33.3 KB transpose (padded)
    __shared__ float         sCs[2][128];
    __shared__ float         r1[256];
    __shared__ float         r2[256];
    __shared__ unsigned      sWd[4];
    __shared__ int           sPc[4];
    __shared__ int           sPref[4];
    __shared__ unsigned char sRank8[128];

    // transpose store (256 threads cover the full 128x64 tile)
#pragma unroll
    for (int k = 0; k < 32; k++) sm[p * 65 + cg * 32 + k] = v[k];
    sCs[cg][p] = csum;
    __syncthreads();

    // mask per position (warps 0-3 hold positions 0..127 in order)
    if (t < 128) {
        bool m = (sCs[0][t] + sCs[1][t]) != 0.0f;
        unsigned ballot = __ballot_sync(0xffffffffu, m);
        if ((t & 31) == 0) {
            int w = t >> 5;
            sWd[w] = ballot;
            sPc[w] = __popc(ballot);
            g_maskbits[b * WH32 + cib * 4 + w] = ballot;
        }
    }
    __syncthreads();

    if (t == 0) {
        sPref[0] = 0;
        sPref[1] = sPc[0];
        sPref[2] = sPc[0] + sPc[1];
        sPref[3] = sPc[0] + sPc[1] + sPc[2];
        atomicAdd(&g_n[b], sPref[3] + sPc[3]);   // off critical path (no consumer here)
    }
    __syncthreads();
    if (t < 128) {
        unsigned w = sWd[t >> 5];
        int bit = t & 31;
        sRank8[t] = (unsigned char)(sPref[t >> 5] + __popc(w & ((1u << bit) - 1u)));
    }
    __syncthreads();

    // compact store from registers into this chunk's STATIC region
    {
        unsigned w = sWd[p >> 5];
        if ((w >> (p & 31)) & 1u) {
            float4* dst = g_compact
                        + ((size_t)blockIdx.x * 128 + sRank8[p]) * 16 + cg * 8;
#pragma unroll
            for (int q = 0; q < 8; q++)
                __stcg(dst + q, make_float4(v[4*q], v[4*q+1], v[4*q+2], v[4*q+3]));
        }
    }

    // per-channel reduction (v dead from here; low pressure)
    const int c = t & 63;
    const int g = t >> 6;
    float a1 = 0.0f, a2 = 0.0f;
#pragma unroll
    for (int i = 0; i < 32; i++) {
        float val = sm[(g * 32 + i) * 65 + c];
        a1 += val;
        a2 += val * val;
    }
    r1[t] = a1;
    r2[t] = a2;
    __syncthreads();

    if (t < CC) {
        float s1 = r1[t] + r1[t + 64] + r1[t + 128] + r1[t + 192];
        float s2 = r2[t] + r2[t + 64] + r2[t + 128] + r2[t + 192];
        const int bkt = blockIdx.x & (NBKT - 1);
        atomicAdd(&g_S1p[bkt][t], s1);
        atomicAdd(&g_S2p[bkt][t], s2);
    }

    // ---- merged finalize: last block computes inv + resets state -----------
    __shared__ bool isLast;
    __shared__ int  spad[BB];
    __shared__ int  sN;
    __threadfence();
    if (t == 0) {
        unsigned int d = atomicAdd(&g_done, 1u);
        isLast = (d == (unsigned int)(NBLOCKS - 1));
    }
    __syncthreads();
    if (!isLast) return;

    if (t == 0) {
        g_done = 0;
        int mx = 0;
#pragma unroll
        for (int bb = 0; bb < BB; bb++) mx = max(mx, g_n[bb]);
        sN = mx;
#pragma unroll
        for (int bb = 0; bb < BB; bb++) {
            spad[bb] = mx - g_n[bb];
            g_n[bb] = 0;
        }
    }
    __syncthreads();
    if (t < CC) {
        float s1 = 0.0f, s2 = 0.0f;
#pragma unroll
        for (int q = 0; q < NBKT; q++) {
            s1 += g_S1p[q][t];
            s2 += g_S2p[q][t];
            g_S1p[q][t] = 0.0f;
            g_S2p[q][t] = 0.0f;
        }
#pragma unroll
        for (int bb = 0; bb < BB; bb++) {
            float x00 = x[(size_t)bb * CC * WH + (size_t)t * WH];
            float pd = (float)spad[bb];
            s1 += pd * x00;
            s2 += pd * x00 * x00;
        }
        float count = (float)BB * (float)sN;
        float mean = s1 / count;
        float var  = s2 / count - mean * mean;
        g_inv[t] = rsqrtf(var + EPSF);
    }
}

// ---------------------------------------------------------------------------
// Pass 2: normalize WITHOUT reading x. One block per 128-position chunk;
// compact values loaded with __ldcg (L2 hits, written by stats with __stcg);
// static chunk base (no dependent global load); hoisted mask/rank logic;
// dense emit with coalesced float4 stores.
// ---------------------------------------------------------------------------
__global__ void __launch_bounds__(256) norm_kernel(float* __restrict__ out) {
    const int b     = blockIdx.y;
    const int chunk = blockIdx.x;       // 0..1673
    const int t     = threadIdx.x;

    __shared__ __align__(16) float         sVal[128 * NPAD];
    __shared__ __align__(16) unsigned char sRank8[128];
    __shared__ unsigned      sW4[4];
    __shared__ int           sPc[4];
    __shared__ int           sPref[4];
    __shared__ int           sCnt_;
    __shared__ float         sInv[CC];

    if (t < 4) {
        unsigned w = g_maskbits[b * WH32 + chunk * 4 + t];
        sW4[t] = w;
        sPc[t] = __popc(w);
    }
    if (t >= 64 && t < 128) sInv[t - 64] = g_inv[t - 64];
    __syncthreads();
    if (t == 0) {
        sPref[0] = 0;
        sPref[1] = sPc[0];
        sPref[2] = sPc[0] + sPc[1];
        sPref[3] = sPc[0] + sPc[1] + sPc[2];
        sCnt_  = sPref[3] + sPc[3];
    }
    __syncthreads();
    if (t < 128) {
        unsigned w = sW4[t >> 5];
        int bit = t & 31;
        sRank8[t] = (unsigned char)(sPref[t >> 5] + __popc(w & ((1u << bit) - 1u)));
    }
    {
        const int E4 = sCnt_ * 16;      // float4 count
        const float4* gin = g_compact + (size_t)(b * CHUNKS + chunk) * 128 * 16;
        for (int i = t; i < E4; i += 256) {
            float4 vv = __ldcg(gin + i);
            *reinterpret_cast<float4*>(&sVal[(i >> 4) * NPAD + (i & 15) * 4]) = vv;
        }
    }
    __syncthreads();

    // hoisted per-thread invariants (independent of channel loop)
    const int p4 = t & 31;
    const int p  = p4 * 4;
    const unsigned w = sW4[p >> 5];
    const int sh = p & 31;
    const bool b0 = (w >> sh)       & 1u;
    const bool b1 = (w >> (sh + 1)) & 1u;
    const bool b2 = (w >> (sh + 2)) & 1u;
    const bool b3 = (w >> (sh + 3)) & 1u;
    const uchar4 rk = *reinterpret_cast<const uchar4*>(&sRank8[p]);
    float4* o4 = reinterpret_cast<float4*>(out)
               + (((size_t)b * CC * WH + (size_t)chunk * 128) >> 2) + p4;

#pragma unroll
    for (int j = 0; j < 8; j++) {
        const int c = j * 8 + (t >> 5);
        const float inv = sInv[c];
        float4 o = make_float4(0.0f, 0.0f, 0.0f, 0.0f);
        if (b0) o.x = sVal[rk.x * NPAD + c] * inv;
        if (b1) o.y = sVal[rk.y * NPAD + c] * inv;
        if (b2) o.z = sVal[rk.z * NPAD + c] * inv;
        if (b3) o.w = sVal[rk.w * NPAD + c] * inv;
        __stcs(o4 + (size_t)c * WH4, o);
    }
}

// ---------------------------------------------------------------------------
extern "C" void kernel_launch(void* const* d_in, const int* in_sizes, int n_in,
                              void* d_out, int out_size) {
    const float* x = (const float*)d_in[0];
    float* out = (float*)d_out;

    stats_kernel<<<NBLOCKS, 256>>>(x);
    dim3 ngrid(CHUNKS, BB);               // (1674, 8)
    norm_kernel<<<ngrid, 256>>>(out);
}